// round 5
// baseline (speedup 1.0000x reference)
#include <cuda_runtime.h>
#include <cuda_fp16.h>
#include <cuda_bf16.h>
#include <cstdint>

#define NN 100000
#define EE 1000000
#define HH 64
#define GG 64
#define CC 3
#define FIN1 32
#define SCAN_BLOCKS 98            // 98*1024 = 100352 >= NN+1

// ---------------- scratch ----------------
__device__ __align__(16) __half g_hp[NN * HH];    // h' = (in@W)*dinv, fp16 rows (128B)
__device__ __align__(16) float g_buf2[NN * HH];   // y  = propagated+b (fp32)
__device__ float g_dinv[NN];
__device__ float g_cnt[GG];
__device__ __align__(16) float g_pooled[GG * HH];
__device__ float g_sum[3 * HH];
__device__ float g_sq[3 * HH];
__device__ float g_scale[3 * HH];
__device__ float g_shift[3 * HH];
// CSR
__device__ int g_deg[NN];
__device__ int g_rowptr[NN + 1];
__device__ int g_next[NN];
__device__ int g_col[EE];
__device__ int g_bsum[SCAN_BLOCKS];

// ---------------- init ----------------
__global__ void init_kernel() {
    int t = blockIdx.x * blockDim.x + threadIdx.x;
    if (t < NN) g_deg[t] = 0;
    if (t < GG * HH) g_pooled[t] = 0.0f;
    if (t < 3 * HH) { g_sum[t] = 0.0f; g_sq[t] = 0.0f; }
    if (t < GG) g_cnt[t] = 0.0f;
}

// ---------------- in-degree histogram ----------------
__global__ void hist_kernel(const int* __restrict__ ei) {
    int e = blockIdx.x * blockDim.x + threadIdx.x;
    if (e < EE) atomicAdd(&g_deg[ei[EE + e]], 1);
}

// ---------------- dinv = rsqrt(deg+1); per-graph counts (warp-aggregated) ----------------
__global__ void dinv_cnt_kernel(const int* __restrict__ batch) {
    int n = blockIdx.x * blockDim.x + threadIdx.x;
    unsigned act = __ballot_sync(0xffffffffu, n < NN);
    if (n < NN) {
        g_dinv[n] = rsqrtf(1.0f + (float)g_deg[n]);
        int g = batch[n];
        unsigned mask = __match_any_sync(act, g);
        int leader = __ffs(mask) - 1;
        if ((int)(threadIdx.x & 31) == leader)
            atomicAdd(&g_cnt[g], (float)__popc(mask));
    }
}

// ---------------- exclusive scan of g_deg -> g_rowptr ----------------
__global__ void scan1_kernel() {
    __shared__ int sh[1024];
    int tid = threadIdx.x;
    int gid = blockIdx.x * 1024 + tid;
    int v = (gid < NN) ? g_deg[gid] : 0;
    sh[tid] = v;
    __syncthreads();
    for (int off = 1; off < 1024; off <<= 1) {
        int t = (tid >= off) ? sh[tid - off] : 0;
        __syncthreads();
        sh[tid] += t;
        __syncthreads();
    }
    if (gid <= NN) g_rowptr[gid] = sh[tid] - v;   // exclusive
    if (tid == 1023) g_bsum[blockIdx.x] = sh[1023];
}

// scan of block sums: 1 block, 128 threads, shuffle scan
__global__ void scan2_kernel() {
    int t = threadIdx.x;
    int lane = t & 31, w = t >> 5;
    int orig = (t < SCAN_BLOCKS) ? g_bsum[t] : 0;
    int v = orig;
#pragma unroll
    for (int off = 1; off < 32; off <<= 1) {
        int u = __shfl_up_sync(0xffffffffu, v, off);
        if (lane >= off) v += u;
    }
    __shared__ int ws[4];
    if (lane == 31) ws[w] = v;
    __syncthreads();
    int add = 0;
    for (int i = 0; i < w; i++) add += ws[i];
    v += add;
    if (t < SCAN_BLOCKS) g_bsum[t] = v - orig;    // exclusive
}

__global__ void scan3_kernel() {
    int gid = blockIdx.x * 1024 + threadIdx.x;
    if (gid <= NN) {
        int v = g_rowptr[gid] + g_bsum[blockIdx.x];
        g_rowptr[gid] = v;
        if (gid < NN) g_next[gid] = v;
    }
}

// ---------------- CSR fill ----------------
__global__ void fill_kernel(const int* __restrict__ ei) {
    int e = blockIdx.x * blockDim.x + threadIdx.x;
    if (e < EE) {
        int dst = ei[EE + e];
        int pos = atomicAdd(&g_next[dst], 1);
        g_col[pos] = ei[e];
    }
}

// ---------------- GEMM: (BN+ReLU of buf2 | x) @ W, * dinv -> g_hp (fp16) ----------------
template <int FIN, int LAYER>
__global__ void __launch_bounds__(256) gemm_kernel(const float* __restrict__ xin,
                                                   const float* __restrict__ W) {
    __shared__ float xs[64][FIN];
    __shared__ float ws[FIN][64];
    const int tid = threadIdx.x;
    const int nbase = blockIdx.x * 64;
    const float* __restrict__ in = (LAYER == 0) ? xin : g_buf2;

    for (int i = tid; i < FIN * 64; i += 256) ws[i >> 6][i & 63] = W[i];

    constexpr int F4 = FIN / 4;
    for (int i = tid; i < 64 * F4; i += 256) {
        int r = i / F4, c4 = i % F4;
        int n = nbase + r;
        float4 v = {0.f, 0.f, 0.f, 0.f};
        if (n < NN) v = *reinterpret_cast<const float4*>(&in[(size_t)n * FIN + c4 * 4]);
        if (LAYER > 0) {
            int c = c4 * 4;
            v.x = fmaxf(fmaf(v.x, g_scale[(LAYER - 1) * HH + c + 0], g_shift[(LAYER - 1) * HH + c + 0]), 0.f);
            v.y = fmaxf(fmaf(v.y, g_scale[(LAYER - 1) * HH + c + 1], g_shift[(LAYER - 1) * HH + c + 1]), 0.f);
            v.z = fmaxf(fmaf(v.z, g_scale[(LAYER - 1) * HH + c + 2], g_shift[(LAYER - 1) * HH + c + 2]), 0.f);
            v.w = fmaxf(fmaf(v.w, g_scale[(LAYER - 1) * HH + c + 3], g_shift[(LAYER - 1) * HH + c + 3]), 0.f);
        }
        *reinterpret_cast<float4*>(&xs[r][c4 * 4]) = v;
    }
    __syncthreads();

    const int cg = tid & 15;          // column group: cols cg*4 .. cg*4+3
    const int n0 = (tid >> 4) * 4;    // nodes n0 .. n0+3
    float4 acc[4] = {{0,0,0,0},{0,0,0,0},{0,0,0,0},{0,0,0,0}};
#pragma unroll
    for (int k4 = 0; k4 < F4; k4++) {
        float4 xv[4];
#pragma unroll
        for (int j = 0; j < 4; j++)
            xv[j] = *reinterpret_cast<const float4*>(&xs[n0 + j][k4 * 4]);
#pragma unroll
        for (int kk = 0; kk < 4; kk++) {
            float4 wv = *reinterpret_cast<const float4*>(&ws[k4 * 4 + kk][cg * 4]);
#pragma unroll
            for (int j = 0; j < 4; j++) {
                float e = (&xv[j].x)[kk];
                acc[j].x = fmaf(e, wv.x, acc[j].x);
                acc[j].y = fmaf(e, wv.y, acc[j].y);
                acc[j].z = fmaf(e, wv.z, acc[j].z);
                acc[j].w = fmaf(e, wv.w, acc[j].w);
            }
        }
    }
#pragma unroll
    for (int j = 0; j < 4; j++) {
        int n = nbase + n0 + j;
        if (n < NN) {
            float dv = g_dinv[n];
            float4 a = acc[j];
            union { uint2 u; __half2 h[2]; } pk;
            pk.h[0] = __floats2half2_rn(a.x * dv, a.y * dv);
            pk.h[1] = __floats2half2_rn(a.z * dv, a.w * dv);
            *reinterpret_cast<uint2*>(&g_hp[(size_t)n * 64 + cg * 4]) = pk.u;
        }
    }
}

// ---------------- fp16 row accumulate helper ----------------
__device__ __forceinline__ void add8(float* acc, float4 v) {
    const __half2* h = reinterpret_cast<const __half2*>(&v);
#pragma unroll
    for (int k = 0; k < 4; k++) {
        float2 f = __half22float2(h[k]);
        acc[2 * k]     += f.x;
        acc[2 * k + 1] += f.y;
    }
}

// ---------------- CSR gather, warp-per-node ----------------
// warp = 1 node; lane = (slot 0..3) * 8 + (q 0..7); slot strides edges, q covers 8 channels.
__global__ void __launch_bounds__(256) gather_kernel(const float* __restrict__ b, int layer) {
    const int tid = threadIdx.x;
    const int lane = tid & 31;
    const int warp = tid >> 5;                    // 0..7
    const int n = blockIdx.x * 8 + warp;          // grid = NN/8 = 12500 exact
    const int slot = lane >> 3;
    const int q = lane & 7;
    const int c0 = q * 8;

    float acc[8] = {0,0,0,0,0,0,0,0};
    if (slot == 0) {   // self term once
        float4 v = *reinterpret_cast<const float4*>(&g_hp[(size_t)n * 64 + c0]);
        add8(acc, v);
    }

    const int beg = g_rowptr[n];
    const int end = g_rowptr[n + 1];
    int i = beg + slot;
    // 2x unroll: 8 independent row loads in flight per warp
    for (; i + 4 < end; i += 8) {
        int s0 = g_col[i];
        int s1 = g_col[i + 4];
        float4 v0 = *reinterpret_cast<const float4*>(&g_hp[(size_t)s0 * 64 + c0]);
        float4 v1 = *reinterpret_cast<const float4*>(&g_hp[(size_t)s1 * 64 + c0]);
        add8(acc, v0);
        add8(acc, v1);
    }
    if (i < end) {
        int s = g_col[i];
        float4 v = *reinterpret_cast<const float4*>(&g_hp[(size_t)s * 64 + c0]);
        add8(acc, v);
    }

    // combine the 4 edge-slots (lanes q, q+8, q+16, q+24 hold same channels)
#pragma unroll
    for (int k = 0; k < 8; k++) {
        acc[k] += __shfl_xor_sync(0xffffffffu, acc[k], 8);
        acc[k] += __shfl_xor_sync(0xffffffffu, acc[k], 16);
    }

    __shared__ float ss[8][64];
    __shared__ float sg[8][64];
    if (lane < 8) {
        const float dv = g_dinv[n];
        float4 bv0 = *reinterpret_cast<const float4*>(&b[c0]);
        float4 bv1 = *reinterpret_cast<const float4*>(&b[c0 + 4]);
        float y[8];
        y[0] = fmaf(acc[0], dv, bv0.x); y[1] = fmaf(acc[1], dv, bv0.y);
        y[2] = fmaf(acc[2], dv, bv0.z); y[3] = fmaf(acc[3], dv, bv0.w);
        y[4] = fmaf(acc[4], dv, bv1.x); y[5] = fmaf(acc[5], dv, bv1.y);
        y[6] = fmaf(acc[6], dv, bv1.z); y[7] = fmaf(acc[7], dv, bv1.w);
        *reinterpret_cast<float4*>(&g_buf2[(size_t)n * 64 + c0])     = make_float4(y[0], y[1], y[2], y[3]);
        *reinterpret_cast<float4*>(&g_buf2[(size_t)n * 64 + c0 + 4]) = make_float4(y[4], y[5], y[6], y[7]);
        *reinterpret_cast<float4*>(&ss[warp][c0])     = make_float4(y[0], y[1], y[2], y[3]);
        *reinterpret_cast<float4*>(&ss[warp][c0 + 4]) = make_float4(y[4], y[5], y[6], y[7]);
        *reinterpret_cast<float4*>(&sg[warp][c0])     = make_float4(y[0]*y[0], y[1]*y[1], y[2]*y[2], y[3]*y[3]);
        *reinterpret_cast<float4*>(&sg[warp][c0 + 4]) = make_float4(y[4]*y[4], y[5]*y[5], y[6]*y[6], y[7]*y[7]);
    }
    __syncthreads();
    if (tid < 64) {
        float a = 0.f, a2 = 0.f;
#pragma unroll
        for (int ww = 0; ww < 8; ww++) { a += ss[ww][tid]; a2 += sg[ww][tid]; }
        atomicAdd(&g_sum[layer * HH + tid], a);
        atomicAdd(&g_sq[layer * HH + tid], a2);
    }
}

// ---------------- BN stats -> scale/shift ----------------
__global__ void stats_kernel(const float* __restrict__ gm, const float* __restrict__ be, int layer) {
    int c = threadIdx.x;   // 64
    float invN = 1.0f / (float)NN;
    float m = g_sum[layer * HH + c] * invN;
    float v = g_sq[layer * HH + c] * invN - m * m;
    float sc = gm[c] * rsqrtf(v + 1e-5f);
    g_scale[layer * HH + c] = sc;
    g_shift[layer * HH + c] = be[c] - m * sc;
}

// ---------------- global mean pool (BN3 applied) ----------------
__global__ void pool_kernel(const int* __restrict__ batch) {
    int t = blockIdx.x * 256 + threadIdx.x;
    int n = t >> 4;
    int q = t & 15;
    int lane = threadIdx.x & 31;
    int g = 0;
    if ((lane & 15) == 0) g = batch[n];
    g = __shfl_sync(0xffffffffu, g, lane & 16);

    int c0 = q * 4;
    float4 v = *reinterpret_cast<const float4*>(&g_buf2[(size_t)n * 64 + c0]);
    float a0 = fmaf(v.x, g_scale[2 * HH + c0 + 0], g_shift[2 * HH + c0 + 0]);
    float a1 = fmaf(v.y, g_scale[2 * HH + c0 + 1], g_shift[2 * HH + c0 + 1]);
    float a2 = fmaf(v.z, g_scale[2 * HH + c0 + 2], g_shift[2 * HH + c0 + 2]);
    float a3 = fmaf(v.w, g_scale[2 * HH + c0 + 3], g_shift[2 * HH + c0 + 3]);
    float* p = &g_pooled[(size_t)g * 64 + c0];
    asm volatile("red.global.add.v4.f32 [%0], {%1,%2,%3,%4};"
                 :: "l"(p), "f"(a0), "f"(a1), "f"(a2), "f"(a3)
                 : "memory");
}

// ---------------- head ----------------
__global__ void head_kernel(const float* __restrict__ Wl1, const float* __restrict__ bl1,
                            const float* __restrict__ Wl2, const float* __restrict__ bl2,
                            float* __restrict__ out) {
    __shared__ float ps[GG][64];
    __shared__ float zs[GG][33];
    __shared__ float lg[GG][3];
    int tid = threadIdx.x;   // 256
    for (int i = tid; i < GG * 64; i += 256) {
        int g = i >> 6;
        ps[g][i & 63] = g_pooled[i] / fmaxf(g_cnt[g], 1.0f);
    }
    __syncthreads();
    for (int i = tid; i < GG * 32; i += 256) {
        int g = i >> 5, j = i & 31;
        float acc = bl1[j];
#pragma unroll
        for (int k = 0; k < 64; k++) acc += ps[g][k] * Wl1[k * 32 + j];
        zs[g][j] = fmaxf(acc, 0.0f);
    }
    __syncthreads();
    if (tid < GG * CC) {
        int g = tid / CC, c = tid % CC;
        float acc = bl2[c];
#pragma unroll
        for (int k = 0; k < 32; k++) acc += zs[g][k] * Wl2[k * CC + c];
        lg[g][c] = acc;
    }
    __syncthreads();
    if (tid < GG) {
        float a = lg[tid][0], b = lg[tid][1], c = lg[tid][2];
        float mx = fmaxf(a, fmaxf(b, c));
        float e0 = expf(a - mx), e1 = expf(b - mx), e2 = expf(c - mx);
        float inv = 1.0f / (e0 + e1 + e2);
        out[tid * 3 + 0] = e0 * inv;
        out[tid * 3 + 1] = e1 * inv;
        out[tid * 3 + 2] = e2 * inv;
    }
}

// ---------------- launch ----------------
extern "C" void kernel_launch(void* const* d_in, const int* in_sizes, int n_in,
                              void* d_out, int out_size) {
    const float* x     = (const float*)d_in[0];
    const int*   ei    = (const int*)d_in[1];
    const int*   batch = (const int*)d_in[2];
    const float* W1  = (const float*)d_in[3];
    const float* b1  = (const float*)d_in[4];
    const float* g1  = (const float*)d_in[5];
    const float* be1 = (const float*)d_in[6];
    const float* W2  = (const float*)d_in[7];
    const float* b2  = (const float*)d_in[8];
    const float* g2  = (const float*)d_in[9];
    const float* be2 = (const float*)d_in[10];
    const float* W3  = (const float*)d_in[11];
    const float* b3  = (const float*)d_in[12];
    const float* g3  = (const float*)d_in[13];
    const float* be3 = (const float*)d_in[14];
    const float* Wl1 = (const float*)d_in[15];
    const float* bl1 = (const float*)d_in[16];
    const float* Wl2 = (const float*)d_in[17];
    const float* bl2 = (const float*)d_in[18];
    float* out = (float*)d_out;

    const int GEMM_GRID   = (NN + 63) / 64;           // 1563
    const int GATHER_GRID = NN / 8;                   // 12500
    const int POOL_GRID   = (NN * 16) / 256;          // 6250

    init_kernel<<<(NN + 255) / 256, 256>>>();
    hist_kernel<<<(EE + 255) / 256, 256>>>(ei);
    dinv_cnt_kernel<<<(NN + 255) / 256, 256>>>(batch);
    scan1_kernel<<<SCAN_BLOCKS, 1024>>>();
    scan2_kernel<<<1, 128>>>();
    scan3_kernel<<<SCAN_BLOCKS, 1024>>>();
    fill_kernel<<<(EE + 255) / 256, 256>>>(ei);

    // ---- layer 1 ----
    gemm_kernel<FIN1, 0><<<GEMM_GRID, 256>>>(x, W1);
    gather_kernel<<<GATHER_GRID, 256>>>(b1, 0);
    stats_kernel<<<1, 64>>>(g1, be1, 0);

    // ---- layer 2 ----
    gemm_kernel<HH, 1><<<GEMM_GRID, 256>>>(nullptr, W2);
    gather_kernel<<<GATHER_GRID, 256>>>(b2, 1);
    stats_kernel<<<1, 64>>>(g2, be2, 1);

    // ---- layer 3 ----
    gemm_kernel<HH, 2><<<GEMM_GRID, 256>>>(nullptr, W3);
    gather_kernel<<<GATHER_GRID, 256>>>(b3, 2);
    stats_kernel<<<1, 64>>>(g3, be3, 2);

    // ---- pool + head ----
    pool_kernel<<<POOL_GRID, 256>>>(batch);
    head_kernel<<<1, 256>>>(Wl1, bl1, Wl2, bl2, out);
}

// round 6
// speedup vs baseline: 1.2579x; 1.2579x over previous
#include <cuda_runtime.h>
#include <cuda_fp16.h>
#include <cuda_bf16.h>
#include <cstdint>

#define NN 100000
#define EE 1000000
#define HH 64
#define GG 64
#define CC 3
#define FIN1 32
#define SCAN_BLOCKS 98            // 98*1024 = 100352 >= NN+1

// ---------------- scratch ----------------
__device__ __align__(16) __half g_hp[NN * HH];     // h' = (in@W)*dinv, fp16 rows (128B)
__device__ __align__(16) __half g_buf2h[NN * HH];  // y  = propagated+b, fp16
__device__ float g_dinv[NN];
__device__ float g_cnt[GG];
__device__ __align__(16) float g_pooled[GG * HH];
__device__ float g_sum[3 * HH];
__device__ float g_sq[3 * HH];
// CSR
__device__ int g_deg[NN];
__device__ int g_rowptr[NN + 1];
__device__ int g_next[NN];
__device__ int g_col[EE + 8];     // +8 pad: unrolled tail may touch past end
__device__ int g_bsum[SCAN_BLOCKS];

// ---------------- init: zero accumulators ----------------
__global__ void init_kernel() {
    int t = blockIdx.x * blockDim.x + threadIdx.x;
    if (t < NN) g_deg[t] = 0;
    if (t < GG * HH) g_pooled[t] = 0.0f;
    if (t < 3 * HH) { g_sum[t] = 0.0f; g_sq[t] = 0.0f; }
    if (t < GG) g_cnt[t] = 0.0f;
}

// ---------------- in-degree histogram ----------------
__global__ void hist_kernel(const int* __restrict__ ei) {
    int e = blockIdx.x * blockDim.x + threadIdx.x;
    if (e < EE) atomicAdd(&g_deg[ei[EE + e]], 1);
}

// ---------------- scan part 1 (+ dinv + per-graph counts, fused) ----------------
__global__ void scan1_kernel(const int* __restrict__ batch) {
    __shared__ int sh[1024];
    int tid = threadIdx.x;
    int gid = blockIdx.x * 1024 + tid;
    int v = (gid < NN) ? g_deg[gid] : 0;
    sh[tid] = v;

    // fused: dinv + warp-aggregated batch counts
    unsigned act = __ballot_sync(0xffffffffu, gid < NN);
    if (gid < NN) {
        g_dinv[gid] = rsqrtf(1.0f + (float)v);
        int g = batch[gid];
        unsigned mask = __match_any_sync(act, g);
        int leader = __ffs(mask) - 1;
        if ((int)(tid & 31) == leader) atomicAdd(&g_cnt[g], (float)__popc(mask));
    }
    __syncthreads();
    for (int off = 1; off < 1024; off <<= 1) {
        int t = (tid >= off) ? sh[tid - off] : 0;
        __syncthreads();
        sh[tid] += t;
        __syncthreads();
    }
    if (gid <= NN) g_rowptr[gid] = sh[tid] - v;   // exclusive
    if (tid == 1023) g_bsum[blockIdx.x] = sh[1023];
}

// scan of block sums: 1 block, 128 threads, shuffle scan
__global__ void scan2_kernel() {
    int t = threadIdx.x;
    int lane = t & 31, w = t >> 5;
    int orig = (t < SCAN_BLOCKS) ? g_bsum[t] : 0;
    int v = orig;
#pragma unroll
    for (int off = 1; off < 32; off <<= 1) {
        int u = __shfl_up_sync(0xffffffffu, v, off);
        if (lane >= off) v += u;
    }
    __shared__ int ws[4];
    if (lane == 31) ws[w] = v;
    __syncthreads();
    int add = 0;
    for (int i = 0; i < w; i++) add += ws[i];
    v += add;
    if (t < SCAN_BLOCKS) g_bsum[t] = v - orig;    // exclusive
}

__global__ void scan3_kernel() {
    int gid = blockIdx.x * 1024 + threadIdx.x;
    if (gid <= NN) {
        int v = g_rowptr[gid] + g_bsum[blockIdx.x];
        g_rowptr[gid] = v;
        if (gid < NN) g_next[gid] = v;
    }
}

// ---------------- CSR fill ----------------
__global__ void fill_kernel(const int* __restrict__ ei) {
    int e = blockIdx.x * blockDim.x + threadIdx.x;
    if (e < EE) {
        int dst = ei[EE + e];
        int pos = atomicAdd(&g_next[dst], 1);
        g_col[pos] = ei[e];
    }
}

// ---------------- GEMM: (BN+ReLU of y | x) @ W, * dinv -> g_hp (fp16) ----------------
// LAYER==0: reads fp32 x. LAYER>0: reads fp16 y, BN scale/shift computed in-block.
template <int FIN, int LAYER>
__global__ void __launch_bounds__(256) gemm_kernel(const float* __restrict__ xin,
                                                   const float* __restrict__ W,
                                                   const float* __restrict__ gm,
                                                   const float* __restrict__ be) {
    __shared__ float xs[64][FIN];
    __shared__ float ws[FIN][64];
    __shared__ float s_scale[64], s_shift[64];
    const int tid = threadIdx.x;
    const int nbase = blockIdx.x * 64;

    if (LAYER > 0 && tid < 64) {
        float invN = 1.0f / (float)NN;
        float m = g_sum[(LAYER - 1) * HH + tid] * invN;
        float v = g_sq[(LAYER - 1) * HH + tid] * invN - m * m;
        float sc = gm[tid] * rsqrtf(v + 1e-5f);
        s_scale[tid] = sc;
        s_shift[tid] = be[tid] - m * sc;
    }

    for (int i = tid; i < FIN * 64; i += 256) ws[i >> 6][i & 63] = W[i];
    if (LAYER > 0) __syncthreads();   // s_scale ready before tile load uses it

    constexpr int F4 = FIN / 4;
    for (int i = tid; i < 64 * F4; i += 256) {
        int r = i / F4, c4 = i % F4;
        int n = nbase + r;
        float4 v = {0.f, 0.f, 0.f, 0.f};
        if (n < NN) {
            if (LAYER == 0) {
                v = *reinterpret_cast<const float4*>(&xin[(size_t)n * FIN + c4 * 4]);
            } else {
                uint2 u = *reinterpret_cast<const uint2*>(&g_buf2h[(size_t)n * 64 + c4 * 4]);
                float2 f0 = __half22float2(*reinterpret_cast<__half2*>(&u.x));
                float2 f1 = __half22float2(*reinterpret_cast<__half2*>(&u.y));
                int c = c4 * 4;
                v.x = fmaxf(fmaf(f0.x, s_scale[c + 0], s_shift[c + 0]), 0.f);
                v.y = fmaxf(fmaf(f0.y, s_scale[c + 1], s_shift[c + 1]), 0.f);
                v.z = fmaxf(fmaf(f1.x, s_scale[c + 2], s_shift[c + 2]), 0.f);
                v.w = fmaxf(fmaf(f1.y, s_scale[c + 3], s_shift[c + 3]), 0.f);
            }
        }
        *reinterpret_cast<float4*>(&xs[r][c4 * 4]) = v;
    }
    __syncthreads();

    const int cg = tid & 15;          // column group: cols cg*4 .. cg*4+3
    const int n0 = (tid >> 4) * 4;    // nodes n0 .. n0+3
    float4 acc[4] = {{0,0,0,0},{0,0,0,0},{0,0,0,0},{0,0,0,0}};
#pragma unroll
    for (int k4 = 0; k4 < F4; k4++) {
        float4 xv[4];
#pragma unroll
        for (int j = 0; j < 4; j++)
            xv[j] = *reinterpret_cast<const float4*>(&xs[n0 + j][k4 * 4]);
#pragma unroll
        for (int kk = 0; kk < 4; kk++) {
            float4 wv = *reinterpret_cast<const float4*>(&ws[k4 * 4 + kk][cg * 4]);
#pragma unroll
            for (int j = 0; j < 4; j++) {
                float e = (&xv[j].x)[kk];
                acc[j].x = fmaf(e, wv.x, acc[j].x);
                acc[j].y = fmaf(e, wv.y, acc[j].y);
                acc[j].z = fmaf(e, wv.z, acc[j].z);
                acc[j].w = fmaf(e, wv.w, acc[j].w);
            }
        }
    }
#pragma unroll
    for (int j = 0; j < 4; j++) {
        int n = nbase + n0 + j;
        if (n < NN) {
            float dv = g_dinv[n];
            float4 a = acc[j];
            union { uint2 u; __half2 h[2]; } pk;
            pk.h[0] = __floats2half2_rn(a.x * dv, a.y * dv);
            pk.h[1] = __floats2half2_rn(a.z * dv, a.w * dv);
            *reinterpret_cast<uint2*>(&g_hp[(size_t)n * 64 + cg * 4]) = pk.u;
        }
    }
}

// ---------------- fp16 row accumulate helper ----------------
__device__ __forceinline__ void add8(float* acc, float4 v) {
    const __half2* h = reinterpret_cast<const __half2*>(&v);
#pragma unroll
    for (int k = 0; k < 4; k++) {
        float2 f = __half22float2(h[k]);
        acc[2 * k]     += f.x;
        acc[2 * k + 1] += f.y;
    }
}

// ---------------- CSR gather: 8 threads/node, 8-deep MLP + predicated tail ----------------
__global__ void __launch_bounds__(256) gather_kernel(const float* __restrict__ b, int layer) {
    const int tid = threadIdx.x;
    const int q = tid & 7;
    const int n = blockIdx.x * 32 + (tid >> 3);   // NN/32 = 3125 exact
    const int c0 = q * 8;

    float acc[8];
    {   // self term
        float4 v = __ldg(reinterpret_cast<const float4*>(&g_hp[(size_t)n * 64 + c0]));
        const __half2* h = reinterpret_cast<const __half2*>(&v);
#pragma unroll
        for (int k = 0; k < 4; k++) {
            float2 f = __half22float2(h[k]);
            acc[2 * k] = f.x; acc[2 * k + 1] = f.y;
        }
    }

    const int beg = g_rowptr[n];
    const int end = g_rowptr[n + 1];
    int i = beg;
    for (; i + 8 <= end; i += 8) {
        int s[8];
#pragma unroll
        for (int k = 0; k < 8; k++) s[k] = __ldg(&g_col[i + k]);
        float4 v[8];
#pragma unroll
        for (int k = 0; k < 8; k++)
            v[k] = __ldg(reinterpret_cast<const float4*>(&g_hp[(size_t)s[k] * 64 + c0]));
#pragma unroll
        for (int k = 0; k < 8; k++) add8(acc, v[k]);
    }
    // predicated 4-wide tail (g_col padded; stray indices hit valid node 0 rows, adds masked)
    for (; i < end; i += 4) {
        int s[4];
#pragma unroll
        for (int k = 0; k < 4; k++) s[k] = __ldg(&g_col[i + k]);
        float4 v[4];
#pragma unroll
        for (int k = 0; k < 4; k++)
            v[k] = __ldg(reinterpret_cast<const float4*>(&g_hp[(size_t)s[k] * 64 + c0]));
#pragma unroll
        for (int k = 0; k < 4; k++) if (i + k < end) add8(acc, v[k]);
    }

    // epilogue: y = acc*dinv + b ; write fp16 y ; BN partial sums
    const float dv = g_dinv[n];
    float4 bv0 = *reinterpret_cast<const float4*>(&b[c0]);
    float4 bv1 = *reinterpret_cast<const float4*>(&b[c0 + 4]);
    float y[8];
    y[0] = fmaf(acc[0], dv, bv0.x); y[1] = fmaf(acc[1], dv, bv0.y);
    y[2] = fmaf(acc[2], dv, bv0.z); y[3] = fmaf(acc[3], dv, bv0.w);
    y[4] = fmaf(acc[4], dv, bv1.x); y[5] = fmaf(acc[5], dv, bv1.y);
    y[6] = fmaf(acc[6], dv, bv1.z); y[7] = fmaf(acc[7], dv, bv1.w);
    union { uint4 u; __half2 h[4]; } pk;
#pragma unroll
    for (int k = 0; k < 4; k++) pk.h[k] = __floats2half2_rn(y[2 * k], y[2 * k + 1]);
    *reinterpret_cast<uint4*>(&g_buf2h[(size_t)n * 64 + c0]) = pk.u;

    float s[8], s2[8];
#pragma unroll
    for (int k = 0; k < 8; k++) { s[k] = y[k]; s2[k] = y[k] * y[k]; }
#pragma unroll
    for (int k = 0; k < 8; k++) {
        s[k]  += __shfl_xor_sync(0xffffffffu, s[k], 8);
        s2[k] += __shfl_xor_sync(0xffffffffu, s2[k], 8);
        s[k]  += __shfl_xor_sync(0xffffffffu, s[k], 16);
        s2[k] += __shfl_xor_sync(0xffffffffu, s2[k], 16);
    }
    __shared__ float ss[8][64];
    __shared__ float sg[8][64];
    int w = tid >> 5, lane = tid & 31;
    if (lane < 8) {
        *reinterpret_cast<float4*>(&ss[w][c0])     = make_float4(s[0], s[1], s[2], s[3]);
        *reinterpret_cast<float4*>(&ss[w][c0 + 4]) = make_float4(s[4], s[5], s[6], s[7]);
        *reinterpret_cast<float4*>(&sg[w][c0])     = make_float4(s2[0], s2[1], s2[2], s2[3]);
        *reinterpret_cast<float4*>(&sg[w][c0 + 4]) = make_float4(s2[4], s2[5], s2[6], s2[7]);
    }
    __syncthreads();
    if (tid < 64) {
        float a = 0.f, a2 = 0.f;
#pragma unroll
        for (int ww = 0; ww < 8; ww++) { a += ss[ww][tid]; a2 += sg[ww][tid]; }
        atomicAdd(&g_sum[layer * HH + tid], a);
        atomicAdd(&g_sq[layer * HH + tid], a2);
    }
}

// ---------------- global mean pool: BN3 (in-block stats) applied to fp16 y ----------------
__global__ void __launch_bounds__(256) pool_kernel(const int* __restrict__ batch,
                                                   const float* __restrict__ gm,
                                                   const float* __restrict__ be) {
    __shared__ float s_scale[64], s_shift[64];
    const int tid = threadIdx.x;
    if (tid < 64) {
        float invN = 1.0f / (float)NN;
        float m = g_sum[2 * HH + tid] * invN;
        float v = g_sq[2 * HH + tid] * invN - m * m;
        float sc = gm[tid] * rsqrtf(v + 1e-5f);
        s_scale[tid] = sc;
        s_shift[tid] = be[tid] - m * sc;
    }
    __syncthreads();

    int t = blockIdx.x * 256 + tid;
    int n = t >> 3;                 // 8 threads/node, grid = NN*8/256 = 3125
    int q = t & 7;
    int lane = tid & 31;
    int g = 0;
    if ((lane & 7) == 0) g = batch[n];
    g = __shfl_sync(0xffffffffu, g, lane & 24);

    int c0 = q * 8;
    uint4 u = *reinterpret_cast<const uint4*>(&g_buf2h[(size_t)n * 64 + c0]);
    const __half2* h = reinterpret_cast<const __half2*>(&u);
    float a[8];
#pragma unroll
    for (int k = 0; k < 4; k++) {
        float2 f = __half22float2(h[k]);
        a[2 * k]     = fmaf(f.x, s_scale[c0 + 2 * k],     s_shift[c0 + 2 * k]);
        a[2 * k + 1] = fmaf(f.y, s_scale[c0 + 2 * k + 1], s_shift[c0 + 2 * k + 1]);
    }
    float* p = &g_pooled[(size_t)g * 64 + c0];
    asm volatile("red.global.add.v4.f32 [%0], {%1,%2,%3,%4};"
                 :: "l"(p), "f"(a[0]), "f"(a[1]), "f"(a[2]), "f"(a[3]) : "memory");
    asm volatile("red.global.add.v4.f32 [%0], {%1,%2,%3,%4};"
                 :: "l"(p + 4), "f"(a[4]), "f"(a[5]), "f"(a[6]), "f"(a[7]) : "memory");
}

// ---------------- head ----------------
__global__ void head_kernel(const float* __restrict__ Wl1, const float* __restrict__ bl1,
                            const float* __restrict__ Wl2, const float* __restrict__ bl2,
                            float* __restrict__ out) {
    __shared__ float ps[GG][64];
    __shared__ float zs[GG][33];
    __shared__ float lg[GG][3];
    int tid = threadIdx.x;   // 256
    for (int i = tid; i < GG * 64; i += 256) {
        int g = i >> 6;
        ps[g][i & 63] = g_pooled[i] / fmaxf(g_cnt[g], 1.0f);
    }
    __syncthreads();
    for (int i = tid; i < GG * 32; i += 256) {
        int g = i >> 5, j = i & 31;
        float acc = bl1[j];
#pragma unroll
        for (int k = 0; k < 64; k++) acc += ps[g][k] * Wl1[k * 32 + j];
        zs[g][j] = fmaxf(acc, 0.0f);
    }
    __syncthreads();
    if (tid < GG * CC) {
        int g = tid / CC, c = tid % CC;
        float acc = bl2[c];
#pragma unroll
        for (int k = 0; k < 32; k++) acc += zs[g][k] * Wl2[k * CC + c];
        lg[g][c] = acc;
    }
    __syncthreads();
    if (tid < GG) {
        float a = lg[tid][0], b = lg[tid][1], c = lg[tid][2];
        float mx = fmaxf(a, fmaxf(b, c));
        float e0 = expf(a - mx), e1 = expf(b - mx), e2 = expf(c - mx);
        float inv = 1.0f / (e0 + e1 + e2);
        out[tid * 3 + 0] = e0 * inv;
        out[tid * 3 + 1] = e1 * inv;
        out[tid * 3 + 2] = e2 * inv;
    }
}

// ---------------- launch ----------------
extern "C" void kernel_launch(void* const* d_in, const int* in_sizes, int n_in,
                              void* d_out, int out_size) {
    const float* x     = (const float*)d_in[0];
    const int*   ei    = (const int*)d_in[1];
    const int*   batch = (const int*)d_in[2];
    const float* W1  = (const float*)d_in[3];
    const float* b1  = (const float*)d_in[4];
    const float* g1  = (const float*)d_in[5];
    const float* be1 = (const float*)d_in[6];
    const float* W2  = (const float*)d_in[7];
    const float* b2  = (const float*)d_in[8];
    const float* g2  = (const float*)d_in[9];
    const float* be2 = (const float*)d_in[10];
    const float* W3  = (const float*)d_in[11];
    const float* b3  = (const float*)d_in[12];
    const float* g3  = (const float*)d_in[13];
    const float* be3 = (const float*)d_in[14];
    const float* Wl1 = (const float*)d_in[15];
    const float* bl1 = (const float*)d_in[16];
    const float* Wl2 = (const float*)d_in[17];
    const float* bl2 = (const float*)d_in[18];
    float* out = (float*)d_out;

    const int GEMM_GRID   = (NN + 63) / 64;           // 1563
    const int GATHER_GRID = NN / 32;                  // 3125
    const int POOL_GRID   = (NN * 8) / 256;           // 3125

    init_kernel<<<(NN + 255) / 256, 256>>>();
    hist_kernel<<<(EE + 255) / 256, 256>>>(ei);
    scan1_kernel<<<SCAN_BLOCKS, 1024>>>(batch);
    scan2_kernel<<<1, 128>>>();
    scan3_kernel<<<SCAN_BLOCKS, 1024>>>();
    fill_kernel<<<(EE + 255) / 256, 256>>>(ei);

    // ---- layer 1 ----
    gemm_kernel<FIN1, 0><<<GEMM_GRID, 256>>>(x, W1, nullptr, nullptr);
    gather_kernel<<<GATHER_GRID, 256>>>(b1, 0);

    // ---- layer 2 ----
    gemm_kernel<HH, 1><<<GEMM_GRID, 256>>>(nullptr, W2, g1, be1);
    gather_kernel<<<GATHER_GRID, 256>>>(b2, 1);

    // ---- layer 3 ----
    gemm_kernel<HH, 2><<<GEMM_GRID, 256>>>(nullptr, W3, g2, be2);
    gather_kernel<<<GATHER_GRID, 256>>>(b3, 2);

    // ---- pool + head ----
    pool_kernel<<<POOL_GRID, 256>>>(batch, g3, be3);
    head_kernel<<<1, 256>>>(Wl1, bl1, Wl2, bl2, out);
}

// round 7
// speedup vs baseline: 1.4297x; 1.1366x over previous
#include <cuda_runtime.h>
#include <cuda_fp16.h>
#include <cuda_bf16.h>
#include <cstdint>

#define NN 100000
#define EE 1000000
#define HH 64
#define GG 64
#define CC 3
#define FIN1 32
#define SCAN_BLOCKS 98            // 98*1024 = 100352 >= NN+1

// ---------------- scratch ----------------
__device__ __align__(16) __half g_hp[NN * HH];     // h' = (in@W)*dinv, fp16 rows (128B)
__device__ __align__(16) __half g_buf2h[NN * HH];  // y  = propagated+b, fp16
__device__ float g_dinv[NN];
__device__ float g_cnt[GG];
__device__ __align__(16) float g_pooled[GG * HH];
__device__ float g_sum[3 * HH];
__device__ float g_sq[3 * HH];
// CSR
__device__ int g_deg[NN];
__device__ int g_rowptr[NN + 1];
__device__ int g_next[NN];
__device__ int g_col[EE + 8];     // +8 pad: unrolled tail may touch past end
__device__ int g_bsum[SCAN_BLOCKS];

__device__ __forceinline__ uint32_t smem_u32(const void* p) {
    return (uint32_t)__cvta_generic_to_shared(p);
}

// ---------------- init: zero accumulators ----------------
__global__ void init_kernel() {
    int t = blockIdx.x * blockDim.x + threadIdx.x;
    if (t < NN) g_deg[t] = 0;
    if (t < GG * HH) g_pooled[t] = 0.0f;
    if (t < 3 * HH) { g_sum[t] = 0.0f; g_sq[t] = 0.0f; }
    if (t < GG) g_cnt[t] = 0.0f;
}

// ---------------- in-degree histogram ----------------
__global__ void hist_kernel(const int* __restrict__ ei) {
    int e = blockIdx.x * blockDim.x + threadIdx.x;
    if (e < EE) atomicAdd(&g_deg[ei[EE + e]], 1);
}

// ---------------- scan part 1 (+ dinv + per-graph counts, fused) ----------------
__global__ void scan1_kernel(const int* __restrict__ batch) {
    __shared__ int sh[1024];
    int tid = threadIdx.x;
    int gid = blockIdx.x * 1024 + tid;
    int v = (gid < NN) ? g_deg[gid] : 0;
    sh[tid] = v;

    unsigned act = __ballot_sync(0xffffffffu, gid < NN);
    if (gid < NN) {
        g_dinv[gid] = rsqrtf(1.0f + (float)v);
        int g = batch[gid];
        unsigned mask = __match_any_sync(act, g);
        int leader = __ffs(mask) - 1;
        if ((int)(tid & 31) == leader) atomicAdd(&g_cnt[g], (float)__popc(mask));
    }
    __syncthreads();
    for (int off = 1; off < 1024; off <<= 1) {
        int t = (tid >= off) ? sh[tid - off] : 0;
        __syncthreads();
        sh[tid] += t;
        __syncthreads();
    }
    if (gid <= NN) g_rowptr[gid] = sh[tid] - v;   // exclusive within block
    if (tid == 1023) g_bsum[blockIdx.x] = sh[1023];   // block total
}

// ---------------- scan3: each block computes its own prefix of block totals ----------------
__global__ void scan3_kernel() {
    __shared__ int soff;
    int tid = threadIdx.x;
    if (tid < 32) {
        int acc = 0;
        for (int j = tid; j < (int)blockIdx.x; j += 32) acc += g_bsum[j];
#pragma unroll
        for (int o = 16; o; o >>= 1) acc += __shfl_xor_sync(0xffffffffu, acc, o);
        if (tid == 0) soff = acc;
    }
    __syncthreads();
    int gid = blockIdx.x * 1024 + tid;
    if (gid <= NN) {
        int v = g_rowptr[gid] + soff;
        g_rowptr[gid] = v;
        if (gid < NN) g_next[gid] = v;
    }
}

// ---------------- CSR fill ----------------
__global__ void fill_kernel(const int* __restrict__ ei) {
    int e = blockIdx.x * blockDim.x + threadIdx.x;
    if (e < EE) {
        int dst = ei[EE + e];
        int pos = atomicAdd(&g_next[dst], 1);
        g_col[pos] = ei[e];
    }
}

// ---------------- GEMM via tensor cores (m16n8k16 f16 mma, f32 accum) ----------------
// Block = 64 nodes x 64 out-cols. 8 warps: warp w -> rows (w&3)*16.., cols (w>>2)*32..
// LAYER==0: x fp32 -> fp16; LAYER>0: y fp16 + in-block BN+ReLU -> fp16.
template <int FIN, int LAYER>
__global__ void __launch_bounds__(256) gemm_kernel(const float* __restrict__ xin,
                                                   const float* __restrict__ W,
                                                   const float* __restrict__ gm,
                                                   const float* __restrict__ be) {
    constexpr int AS = FIN + 8;   // A smem stride (halves)
    constexpr int BS = HH + 8;    // W smem stride (halves)
    __shared__ __half xs[64 * AS];
    __shared__ __half ws[FIN * BS];
    __shared__ float sdinv[64];
    __shared__ float s_scale[64], s_shift[64];

    const int tid = threadIdx.x;
    const int nbase = blockIdx.x * 64;

    if (LAYER > 0 && tid < 64) {
        float invN = 1.0f / (float)NN;
        float m = g_sum[(LAYER - 1) * HH + tid] * invN;
        float v = g_sq[(LAYER - 1) * HH + tid] * invN - m * m;
        float sc = gm[tid] * rsqrtf(v + 1e-5f);
        s_scale[tid] = sc;
        s_shift[tid] = be[tid] - m * sc;
    }
    if (tid < 64) {
        int n = nbase + tid;
        sdinv[tid] = (n < NN) ? g_dinv[n] : 0.0f;
    }
    // W: [FIN][64] fp32 -> fp16 smem
    for (int i = tid; i < FIN * HH; i += 256)
        ws[(i >> 6) * BS + (i & 63)] = __float2half(W[i]);
    if (LAYER > 0) __syncthreads();   // s_scale ready before staging

    // A staging: 4-col chunks
    constexpr int F4 = FIN / 4;
    for (int i = tid; i < 64 * F4; i += 256) {
        int r = i / F4, c4 = i % F4;
        int n = nbase + r;
        int c = c4 * 4;
        float v0 = 0.f, v1 = 0.f, v2 = 0.f, v3 = 0.f;
        if (n < NN) {
            if (LAYER == 0) {
                float4 v = *reinterpret_cast<const float4*>(&xin[(size_t)n * FIN + c]);
                v0 = v.x; v1 = v.y; v2 = v.z; v3 = v.w;
            } else {
                uint2 u = *reinterpret_cast<const uint2*>(&g_buf2h[(size_t)n * 64 + c]);
                float2 f0 = __half22float2(*reinterpret_cast<__half2*>(&u.x));
                float2 f1 = __half22float2(*reinterpret_cast<__half2*>(&u.y));
                v0 = fmaxf(fmaf(f0.x, s_scale[c + 0], s_shift[c + 0]), 0.f);
                v1 = fmaxf(fmaf(f0.y, s_scale[c + 1], s_shift[c + 1]), 0.f);
                v2 = fmaxf(fmaf(f1.x, s_scale[c + 2], s_shift[c + 2]), 0.f);
                v3 = fmaxf(fmaf(f1.y, s_scale[c + 3], s_shift[c + 3]), 0.f);
            }
        }
        union { uint2 u; __half2 h[2]; } pk;
        pk.h[0] = __floats2half2_rn(v0, v1);
        pk.h[1] = __floats2half2_rn(v2, v3);
        *reinterpret_cast<uint2*>(&xs[r * AS + c]) = pk.u;
    }
    __syncthreads();

    const int w = tid >> 5, lane = tid & 31;
    const int mw = (w & 3) * 16;        // warp row base
    const int nb = (w >> 2) * 32;       // warp col base
    float acc[4][4] = {{0,0,0,0},{0,0,0,0},{0,0,0,0},{0,0,0,0}};

    const uint32_t xs_base = smem_u32(xs);
    const uint32_t ws_base = smem_u32(ws);

#pragma unroll
    for (int k0 = 0; k0 < FIN; k0 += 16) {
        uint32_t a0, a1, a2, a3;
        uint32_t a_addr = xs_base + ((mw + (lane & 15)) * AS + k0 + ((lane >> 4) * 8)) * 2;
        asm volatile("ldmatrix.sync.aligned.m8n8.x4.shared.b16 {%0,%1,%2,%3}, [%4];"
                     : "=r"(a0), "=r"(a1), "=r"(a2), "=r"(a3) : "r"(a_addr));
#pragma unroll
        for (int hn = 0; hn < 2; hn++) {
            uint32_t b0, b1, b2, b3;
            uint32_t b_addr = ws_base + ((k0 + (lane & 15)) * BS + nb + hn * 16 + ((lane >> 4) * 8)) * 2;
            asm volatile("ldmatrix.sync.aligned.m8n8.x4.trans.shared.b16 {%0,%1,%2,%3}, [%4];"
                         : "=r"(b0), "=r"(b1), "=r"(b2), "=r"(b3) : "r"(b_addr));
            asm volatile("mma.sync.aligned.m16n8k16.row.col.f32.f16.f16.f32 "
                         "{%0,%1,%2,%3}, {%4,%5,%6,%7}, {%8,%9}, {%0,%1,%2,%3};"
                         : "+f"(acc[hn * 2][0]), "+f"(acc[hn * 2][1]),
                           "+f"(acc[hn * 2][2]), "+f"(acc[hn * 2][3])
                         : "r"(a0), "r"(a1), "r"(a2), "r"(a3), "r"(b0), "r"(b1));
            asm volatile("mma.sync.aligned.m16n8k16.row.col.f32.f16.f16.f32 "
                         "{%0,%1,%2,%3}, {%4,%5,%6,%7}, {%8,%9}, {%0,%1,%2,%3};"
                         : "+f"(acc[hn * 2 + 1][0]), "+f"(acc[hn * 2 + 1][1]),
                           "+f"(acc[hn * 2 + 1][2]), "+f"(acc[hn * 2 + 1][3])
                         : "r"(a0), "r"(a1), "r"(a2), "r"(a3), "r"(b2), "r"(b3));
        }
    }

    // epilogue: rows r0 = mw + lane/4, r1 = r0+8 ; cols nb + nt*8 + (lane&3)*2
    const int r0 = mw + (lane >> 2);
    const int r1 = r0 + 8;
    const int n0 = nbase + r0, n1 = nbase + r1;
    const float dv0 = sdinv[r0], dv1 = sdinv[r1];
#pragma unroll
    for (int nt = 0; nt < 4; nt++) {
        int c = nb + nt * 8 + (lane & 3) * 2;
        if (n0 < NN)
            *reinterpret_cast<__half2*>(&g_hp[(size_t)n0 * 64 + c]) =
                __floats2half2_rn(acc[nt][0] * dv0, acc[nt][1] * dv0);
        if (n1 < NN)
            *reinterpret_cast<__half2*>(&g_hp[(size_t)n1 * 64 + c]) =
                __floats2half2_rn(acc[nt][2] * dv1, acc[nt][3] * dv1);
    }
}

// ---------------- fp16 row accumulate helper ----------------
__device__ __forceinline__ void add8(float* acc, float4 v) {
    const __half2* h = reinterpret_cast<const __half2*>(&v);
#pragma unroll
    for (int k = 0; k < 4; k++) {
        float2 f = __half22float2(h[k]);
        acc[2 * k]     += f.x;
        acc[2 * k + 1] += f.y;
    }
}

// ---------------- CSR gather: 8 threads/node, 8-deep MLP + predicated tail ----------------
__global__ void __launch_bounds__(256) gather_kernel(const float* __restrict__ b, int layer) {
    const int tid = threadIdx.x;
    const int q = tid & 7;
    const int n = blockIdx.x * 32 + (tid >> 3);   // NN/32 = 3125 exact
    const int c0 = q * 8;

    float acc[8];
    {   // self term
        float4 v = __ldg(reinterpret_cast<const float4*>(&g_hp[(size_t)n * 64 + c0]));
        const __half2* h = reinterpret_cast<const __half2*>(&v);
#pragma unroll
        for (int k = 0; k < 4; k++) {
            float2 f = __half22float2(h[k]);
            acc[2 * k] = f.x; acc[2 * k + 1] = f.y;
        }
    }

    const int beg = g_rowptr[n];
    const int end = g_rowptr[n + 1];
    int i = beg;
    for (; i + 8 <= end; i += 8) {
        int s[8];
#pragma unroll
        for (int k = 0; k < 8; k++) s[k] = __ldg(&g_col[i + k]);
        float4 v[8];
#pragma unroll
        for (int k = 0; k < 8; k++)
            v[k] = __ldg(reinterpret_cast<const float4*>(&g_hp[(size_t)s[k] * 64 + c0]));
#pragma unroll
        for (int k = 0; k < 8; k++) add8(acc, v[k]);
    }
    for (; i < end; i += 4) {
        int s[4];
#pragma unroll
        for (int k = 0; k < 4; k++) s[k] = __ldg(&g_col[i + k]);
        float4 v[4];
#pragma unroll
        for (int k = 0; k < 4; k++)
            v[k] = __ldg(reinterpret_cast<const float4*>(&g_hp[(size_t)s[k] * 64 + c0]));
#pragma unroll
        for (int k = 0; k < 4; k++) if (i + k < end) add8(acc, v[k]);
    }

    const float dv = g_dinv[n];
    float4 bv0 = *reinterpret_cast<const float4*>(&b[c0]);
    float4 bv1 = *reinterpret_cast<const float4*>(&b[c0 + 4]);
    float y[8];
    y[0] = fmaf(acc[0], dv, bv0.x); y[1] = fmaf(acc[1], dv, bv0.y);
    y[2] = fmaf(acc[2], dv, bv0.z); y[3] = fmaf(acc[3], dv, bv0.w);
    y[4] = fmaf(acc[4], dv, bv1.x); y[5] = fmaf(acc[5], dv, bv1.y);
    y[6] = fmaf(acc[6], dv, bv1.z); y[7] = fmaf(acc[7], dv, bv1.w);
    union { uint4 u; __half2 h[4]; } pk;
#pragma unroll
    for (int k = 0; k < 4; k++) pk.h[k] = __floats2half2_rn(y[2 * k], y[2 * k + 1]);
    *reinterpret_cast<uint4*>(&g_buf2h[(size_t)n * 64 + c0]) = pk.u;

    float s[8], s2[8];
#pragma unroll
    for (int k = 0; k < 8; k++) { s[k] = y[k]; s2[k] = y[k] * y[k]; }
#pragma unroll
    for (int k = 0; k < 8; k++) {
        s[k]  += __shfl_xor_sync(0xffffffffu, s[k], 8);
        s2[k] += __shfl_xor_sync(0xffffffffu, s2[k], 8);
        s[k]  += __shfl_xor_sync(0xffffffffu, s[k], 16);
        s2[k] += __shfl_xor_sync(0xffffffffu, s2[k], 16);
    }
    __shared__ float ss[8][64];
    __shared__ float sg[8][64];
    int w = tid >> 5, lane = tid & 31;
    if (lane < 8) {
        *reinterpret_cast<float4*>(&ss[w][c0])     = make_float4(s[0], s[1], s[2], s[3]);
        *reinterpret_cast<float4*>(&ss[w][c0 + 4]) = make_float4(s[4], s[5], s[6], s[7]);
        *reinterpret_cast<float4*>(&sg[w][c0])     = make_float4(s2[0], s2[1], s2[2], s2[3]);
        *reinterpret_cast<float4*>(&sg[w][c0 + 4]) = make_float4(s2[4], s2[5], s2[6], s2[7]);
    }
    __syncthreads();
    if (tid < 64) {
        float a = 0.f, a2 = 0.f;
#pragma unroll
        for (int ww = 0; ww < 8; ww++) { a += ss[ww][tid]; a2 += sg[ww][tid]; }
        atomicAdd(&g_sum[layer * HH + tid], a);
        atomicAdd(&g_sq[layer * HH + tid], a2);
    }
}

// ---------------- global mean pool: BN3 (in-block stats) applied to fp16 y ----------------
__global__ void __launch_bounds__(256) pool_kernel(const int* __restrict__ batch,
                                                   const float* __restrict__ gm,
                                                   const float* __restrict__ be) {
    __shared__ float s_scale[64], s_shift[64];
    const int tid = threadIdx.x;
    if (tid < 64) {
        float invN = 1.0f / (float)NN;
        float m = g_sum[2 * HH + tid] * invN;
        float v = g_sq[2 * HH + tid] * invN - m * m;
        float sc = gm[tid] * rsqrtf(v + 1e-5f);
        s_scale[tid] = sc;
        s_shift[tid] = be[tid] - m * sc;
    }
    __syncthreads();

    int t = blockIdx.x * 256 + tid;
    int n = t >> 3;                 // 8 threads/node, grid = NN*8/256 = 3125
    int q = t & 7;
    int lane = tid & 31;
    int g = 0;
    if ((lane & 7) == 0) g = batch[n];
    g = __shfl_sync(0xffffffffu, g, lane & 24);

    int c0 = q * 8;
    uint4 u = *reinterpret_cast<const uint4*>(&g_buf2h[(size_t)n * 64 + c0]);
    const __half2* h = reinterpret_cast<const __half2*>(&u);
    float a[8];
#pragma unroll
    for (int k = 0; k < 4; k++) {
        float2 f = __half22float2(h[k]);
        a[2 * k]     = fmaf(f.x, s_scale[c0 + 2 * k],     s_shift[c0 + 2 * k]);
        a[2 * k + 1] = fmaf(f.y, s_scale[c0 + 2 * k + 1], s_shift[c0 + 2 * k + 1]);
    }
    float* p = &g_pooled[(size_t)g * 64 + c0];
    asm volatile("red.global.add.v4.f32 [%0], {%1,%2,%3,%4};"
                 :: "l"(p), "f"(a[0]), "f"(a[1]), "f"(a[2]), "f"(a[3]) : "memory");
    asm volatile("red.global.add.v4.f32 [%0], {%1,%2,%3,%4};"
                 :: "l"(p + 4), "f"(a[4]), "f"(a[5]), "f"(a[6]), "f"(a[7]) : "memory");
}

// ---------------- head ----------------
__global__ void head_kernel(const float* __restrict__ Wl1, const float* __restrict__ bl1,
                            const float* __restrict__ Wl2, const float* __restrict__ bl2,
                            float* __restrict__ out) {
    __shared__ float ps[GG][64];
    __shared__ float zs[GG][33];
    __shared__ float lg[GG][3];
    int tid = threadIdx.x;   // 256
    for (int i = tid; i < GG * 64; i += 256) {
        int g = i >> 6;
        ps[g][i & 63] = g_pooled[i] / fmaxf(g_cnt[g], 1.0f);
    }
    __syncthreads();
    for (int i = tid; i < GG * 32; i += 256) {
        int g = i >> 5, j = i & 31;
        float acc = bl1[j];
#pragma unroll
        for (int k = 0; k < 64; k++) acc += ps[g][k] * Wl1[k * 32 + j];
        zs[g][j] = fmaxf(acc, 0.0f);
    }
    __syncthreads();
    if (tid < GG * CC) {
        int g = tid / CC, c = tid % CC;
        float acc = bl2[c];
#pragma unroll
        for (int k = 0; k < 32; k++) acc += zs[g][k] * Wl2[k * CC + c];
        lg[g][c] = acc;
    }
    __syncthreads();
    if (tid < GG) {
        float a = lg[tid][0], b = lg[tid][1], c = lg[tid][2];
        float mx = fmaxf(a, fmaxf(b, c));
        float e0 = expf(a - mx), e1 = expf(b - mx), e2 = expf(c - mx);
        float inv = 1.0f / (e0 + e1 + e2);
        out[tid * 3 + 0] = e0 * inv;
        out[tid * 3 + 1] = e1 * inv;
        out[tid * 3 + 2] = e2 * inv;
    }
}

// ---------------- launch ----------------
extern "C" void kernel_launch(void* const* d_in, const int* in_sizes, int n_in,
                              void* d_out, int out_size) {
    const float* x     = (const float*)d_in[0];
    const int*   ei    = (const int*)d_in[1];
    const int*   batch = (const int*)d_in[2];
    const float* W1  = (const float*)d_in[3];
    const float* b1  = (const float*)d_in[4];
    const float* g1  = (const float*)d_in[5];
    const float* be1 = (const float*)d_in[6];
    const float* W2  = (const float*)d_in[7];
    const float* b2  = (const float*)d_in[8];
    const float* g2  = (const float*)d_in[9];
    const float* be2 = (const float*)d_in[10];
    const float* W3  = (const float*)d_in[11];
    const float* b3  = (const float*)d_in[12];
    const float* g3  = (const float*)d_in[13];
    const float* be3 = (const float*)d_in[14];
    const float* Wl1 = (const float*)d_in[15];
    const float* bl1 = (const float*)d_in[16];
    const float* Wl2 = (const float*)d_in[17];
    const float* bl2 = (const float*)d_in[18];
    float* out = (float*)d_out;

    const int GEMM_GRID   = (NN + 63) / 64;           // 1563
    const int GATHER_GRID = NN / 32;                  // 3125
    const int POOL_GRID   = (NN * 8) / 256;           // 3125

    init_kernel<<<(NN + 255) / 256, 256>>>();
    hist_kernel<<<(EE + 255) / 256, 256>>>(ei);
    scan1_kernel<<<SCAN_BLOCKS, 1024>>>(batch);
    scan3_kernel<<<SCAN_BLOCKS, 1024>>>();
    fill_kernel<<<(EE + 255) / 256, 256>>>(ei);

    // ---- layer 1 ----
    gemm_kernel<FIN1, 0><<<GEMM_GRID, 256>>>(x, W1, nullptr, nullptr);
    gather_kernel<<<GATHER_GRID, 256>>>(b1, 0);

    // ---- layer 2 ----
    gemm_kernel<HH, 1><<<GEMM_GRID, 256>>>(nullptr, W2, g1, be1);
    gather_kernel<<<GATHER_GRID, 256>>>(b2, 1);

    // ---- layer 3 ----
    gemm_kernel<HH, 2><<<GEMM_GRID, 256>>>(nullptr, W3, g2, be2);
    gather_kernel<<<GATHER_GRID, 256>>>(b3, 2);

    // ---- pool + head ----
    pool_kernel<<<POOL_GRID, 256>>>(batch, g3, be3);
    head_kernel<<<1, 256>>>(Wl1, bl1, Wl2, bl2, out);
}